// round 10
// baseline (speedup 1.0000x reference)
#include <cuda_runtime.h>
#include <cuda_fp16.h>
#include <cstdint>

constexpr int USER_NUM = 200000;
constexpr int ITEM_NUM = 100000;
constexpr int N_NODES  = USER_NUM + ITEM_NUM;   // 300000
constexpr int NNZ      = 12800000;
constexpr int U4       = USER_NUM * 16;         // user float4 count
constexpr int H8       = 8;                     // uint4 (8 halves) per 64-wide fp16 row
constexpr int NH       = N_NODES * H8;          // 2.4M uint4 per fp16 buffer
constexpr int CAP      = 96;                    // per-row degree cap (mean 42.7, max ~78)
constexpr int BKT_MAX  = NNZ + 8 * N_NODES;     // compact CSR upper bound (15.2M)
constexpr int SCB      = 4096;                  // elements per scan block
constexpr int NB_SCAN  = (N_NODES + SCB - 1) / SCB;   // 74

// Static device scratch
__device__ uint4 g_bufA[NH];                    // 38.4 MB fp16 (e0)
__device__ uint4 g_bufB[NH];                    // 38.4 MB fp16 (e1)
__device__ uint4 g_bufC[NH];                    // 38.4 MB fp16 (e2)
__device__ int2  g_bkt[BKT_MAX];                // 121.6 MB compact (col, val_bits)
__device__ int   g_cnt[N_NODES];
__device__ int   g_offs[N_NODES + 1];           // padded CSR offsets (multiples of 8)
__device__ int   g_cur[N_NODES];                // fill cursors
__device__ int   g_bsum[NB_SCAN];
__device__ int   g_boff[NB_SCAN + 1];

__device__ __forceinline__ uint32_t f22h(float a, float b) {
    __half2 h = __floats2half2_rn(a, b);
    return reinterpret_cast<uint32_t&>(h);
}
__device__ __forceinline__ float2 h22f(uint32_t u) {
    __half2 h = reinterpret_cast<__half2&>(u);
    return __half22float2(h);
}

// ---------------------------------------------------------------------------
// init: bufA = fp16(concat(user, item)); cnt = 0.
// ---------------------------------------------------------------------------
__global__ void init_kernel(const float4* __restrict__ user,
                            const float4* __restrict__ item,
                            uint4* __restrict__ bufA,
                            int* __restrict__ cnt) {
    int i = blockIdx.x * blockDim.x + threadIdx.x;
    if (i < N_NODES) cnt[i] = 0;
    if (i >= NH) return;
    int f = i * 2;                              // float4 index (U4 is even)
    float4 x = (f < U4) ? __ldg(user + f)     : __ldg(item + f - U4);
    float4 y = (f < U4) ? __ldg(user + f + 1) : __ldg(item + f + 1 - U4);
    uint4 h;
    h.x = f22h(x.x, x.y);
    h.y = f22h(x.z, x.w);
    h.z = f22h(y.x, y.y);
    h.w = f22h(y.z, y.w);
    bufA[i] = h;
}

// ---------------------------------------------------------------------------
// hist: per-row degree counts (rows only, 4 edges/thread).
// ---------------------------------------------------------------------------
__global__ void hist_kernel(const int4* __restrict__ rows4, int* __restrict__ cnt) {
    int t = blockIdx.x * blockDim.x + threadIdx.x;
    if (t >= NNZ / 4) return;
    int4 r = __ldcs(rows4 + t);
    atomicAdd(cnt + r.x, 1);
    atomicAdd(cnt + r.y, 1);
    atomicAdd(cnt + r.z, 1);
    atomicAdd(cnt + r.w, 1);
}

__device__ __forceinline__ int padded_cnt(const int* cnt, int i) {
    return (i < N_NODES) ? ((min(__ldg(cnt + i), CAP) + 7) & ~7) : 0;
}

// ---------------------------------------------------------------------------
// scan1: per-block (4096 elems) sums of padded counts.
// ---------------------------------------------------------------------------
__global__ void scan1_kernel(const int* __restrict__ cnt, int* __restrict__ bsum) {
    int b = blockIdx.x, t = threadIdx.x;
    int i0 = b * SCB + t * 4;
    int s = padded_cnt(cnt, i0) + padded_cnt(cnt, i0 + 1)
          + padded_cnt(cnt, i0 + 2) + padded_cnt(cnt, i0 + 3);
    #pragma unroll
    for (int o = 16; o; o >>= 1) s += __shfl_xor_sync(~0u, s, o);
    __shared__ int ws[32];
    if ((t & 31) == 0) ws[t >> 5] = s;
    __syncthreads();
    if (t < 32) {
        int v = ws[t];
        #pragma unroll
        for (int o = 16; o; o >>= 1) v += __shfl_xor_sync(~0u, v, o);
        if (t == 0) bsum[b] = v;
    }
}

// ---------------------------------------------------------------------------
// scan2: exclusive scan of the 74 block sums (one 128-thread block).
// ---------------------------------------------------------------------------
__global__ void scan2_kernel(const int* __restrict__ bsum,
                             int* __restrict__ boff, int* __restrict__ offs) {
    __shared__ int s[128];
    int t = threadIdx.x;
    int v = (t < NB_SCAN) ? bsum[t] : 0;
    s[t] = v;
    __syncthreads();
    for (int o = 1; o < 128; o <<= 1) {
        int u = (t >= o) ? s[t - o] : 0;
        __syncthreads();
        s[t] += u;
        __syncthreads();
    }
    if (t < NB_SCAN) boff[t] = s[t] - v;
    if (t == 127) { boff[NB_SCAN] = s[127]; offs[N_NODES] = s[127]; }
}

// ---------------------------------------------------------------------------
// scan3: final padded offsets + cursors.
// ---------------------------------------------------------------------------
__global__ void scan3_kernel(const int* __restrict__ cnt,
                             const int* __restrict__ boff,
                             int* __restrict__ offs, int* __restrict__ cur) {
    int b = blockIdx.x, t = threadIdx.x, lane = t & 31, w = t >> 5;
    int i0 = b * SCB + t * 4;
    int p0 = padded_cnt(cnt, i0),     p1 = padded_cnt(cnt, i0 + 1);
    int p2 = padded_cnt(cnt, i0 + 2), p3 = padded_cnt(cnt, i0 + 3);
    int s = p0 + p1 + p2 + p3;
    int incl = s;
    #pragma unroll
    for (int o = 1; o < 32; o <<= 1) {
        int u = __shfl_up_sync(~0u, incl, o);
        if (lane >= o) incl += u;
    }
    __shared__ int ws[32], wb[32];
    if (lane == 31) ws[w] = incl;
    __syncthreads();
    if (t < 32) {
        int v = ws[t], iv = v;
        #pragma unroll
        for (int o = 1; o < 32; o <<= 1) {
            int u = __shfl_up_sync(~0u, iv, o);
            if (t >= o) iv += u;
        }
        wb[t] = iv - v;
    }
    __syncthreads();
    int base = __ldg(boff + b) + wb[w] + (incl - s);
    int i = i0;
    if (i < N_NODES) { offs[i] = base; cur[i] = base; } base += p0; i++;
    if (i < N_NODES) { offs[i] = base; cur[i] = base; } base += p1; i++;
    if (i < N_NODES) { offs[i] = base; cur[i] = base; } base += p2; i++;
    if (i < N_NODES) { offs[i] = base; cur[i] = base; }
}

// ---------------------------------------------------------------------------
// pad: zero the <=7 padding slots per row (disjoint from fill's slots).
// ---------------------------------------------------------------------------
__global__ void pad_kernel(int2* __restrict__ bkt,
                           const int* __restrict__ cnt,
                           const int* __restrict__ offs) {
    int r = blockIdx.x * blockDim.x + threadIdx.x;
    if (r >= N_NODES) return;
    int n = min(__ldg(cnt + r), CAP);
    int o = __ldg(offs + r) + n;
    int e = __ldg(offs + r + 1);
    for (int i = o; i < e; ++i) bkt[i] = make_int2(0, 0);
}

// ---------------------------------------------------------------------------
// fill: scatter edges into the compact CSR array (4 edges/thread).
// Guard against (statistically impossible) CAP overflow via offs[r+1].
// ---------------------------------------------------------------------------
__global__ void fill_kernel(const int4*   __restrict__ rows4,
                            const int4*   __restrict__ cols4,
                            const float4* __restrict__ vals4,
                            const int*    __restrict__ offs,
                            int2* __restrict__ bkt,
                            int*  __restrict__ cur) {
    int t = blockIdx.x * blockDim.x + threadIdx.x;
    if (t >= NNZ / 4) return;
    int4   r = __ldcs(rows4 + t);
    int4   c = __ldcs(cols4 + t);
    float4 v = __ldcs(vals4 + t);

    int p0 = atomicAdd(cur + r.x, 1);
    if (p0 < __ldg(offs + r.x + 1)) bkt[p0] = make_int2(c.x, __float_as_int(v.x));
    int p1 = atomicAdd(cur + r.y, 1);
    if (p1 < __ldg(offs + r.y + 1)) bkt[p1] = make_int2(c.y, __float_as_int(v.y));
    int p2 = atomicAdd(cur + r.z, 1);
    if (p2 < __ldg(offs + r.z + 1)) bkt[p2] = make_int2(c.z, __float_as_int(v.z));
    int p3 = atomicAdd(cur + r.w, 1);
    if (p3 < __ldg(offs + r.w + 1)) bkt[p3] = make_int2(c.w, __float_as_int(v.w));
}

// ---------------------------------------------------------------------------
// spmm: round-5 proven body (regs 32, occ ~84%), CSR addressing only change.
// One warp per destination row; four 8-lane edge sub-streams; one LDG.128
// warp-instruction gathers FOUR edges' 8-half slices; fp32 FFMA path.
// final==0: dst[row] = fp16(acc).   final==1: out[row] = 0.25*(e0+e1+e2+acc).
// ---------------------------------------------------------------------------
__global__ void __launch_bounds__(256)
spmm_kernel(const int2* __restrict__ bkt,
            const int*  __restrict__ offs,
            const uint4* __restrict__ src,
            uint4* __restrict__ dst,
            const uint4* __restrict__ eA,
            const uint4* __restrict__ eB,
            float4* __restrict__ out,
            int final_) {
    int warp = (blockIdx.x * blockDim.x + threadIdx.x) >> 5;
    int lane = threadIdx.x & 31;
    if (warp >= N_NODES) return;
    int sub = lane >> 3;       // edge sub-stream 0..3
    int l8  = lane & 7;        // uint4 slot within row

    int o0 = __ldg(offs + warp);
    int n8 = __ldg(offs + warp + 1) - o0;       // always a multiple of 8
    const int2* base = bkt + o0;

    float acc[8];
    #pragma unroll
    for (int k = 0; k < 8; ++k) acc[k] = 0.f;

    // software-pipelined edge metadata
    int2 p0 = make_int2(0, 0), p1 = make_int2(0, 0);
    if (n8 > 0) { p0 = __ldcs(base + sub); p1 = __ldcs(base + 4 + sub); }

    for (int c = 0; c < n8; c += 8) {
        int2 f0 = p0, f1 = p1;
        if (c + 8 < n8) {
            p0 = __ldcs(base + c + 8  + sub);
            p1 = __ldcs(base + c + 12 + sub);
        }
        {
            uint4 h = __ldg(src + f0.x * H8 + l8);
            float v = __int_as_float(f0.y);
            float2 a = h22f(h.x), b = h22f(h.y), cc = h22f(h.z), d = h22f(h.w);
            acc[0] += v * a.x; acc[1] += v * a.y;
            acc[2] += v * b.x; acc[3] += v * b.y;
            acc[4] += v * cc.x; acc[5] += v * cc.y;
            acc[6] += v * d.x; acc[7] += v * d.y;
        }
        {
            uint4 h = __ldg(src + f1.x * H8 + l8);
            float v = __int_as_float(f1.y);
            float2 a = h22f(h.x), b = h22f(h.y), cc = h22f(h.z), d = h22f(h.w);
            acc[0] += v * a.x; acc[1] += v * a.y;
            acc[2] += v * b.x; acc[3] += v * b.y;
            acc[4] += v * cc.x; acc[5] += v * cc.y;
            acc[6] += v * d.x; acc[7] += v * d.y;
        }
    }

    // combine the four sub-streams
    #pragma unroll
    for (int k = 0; k < 8; ++k) {
        acc[k] += __shfl_xor_sync(0xffffffffu, acc[k], 8);
        acc[k] += __shfl_xor_sync(0xffffffffu, acc[k], 16);
    }

    if (sub == 0) {
        int o = warp * H8 + l8;
        if (!final_) {
            uint4 h;
            h.x = f22h(acc[0], acc[1]);
            h.y = f22h(acc[2], acc[3]);
            h.z = f22h(acc[4], acc[5]);
            h.w = f22h(acc[6], acc[7]);
            dst[o] = h;
        } else {
            uint4 ha = __ldg(eA + o);
            uint4 hb = __ldg(eB + o);
            uint4 hc = __ldg(src + o);      // src == e2 buffer in final layer
            float2 a0 = h22f(ha.x), a1 = h22f(ha.y), a2 = h22f(ha.z), a3 = h22f(ha.w);
            float2 b0 = h22f(hb.x), b1 = h22f(hb.y), b2 = h22f(hb.z), b3 = h22f(hb.w);
            float2 c0 = h22f(hc.x), c1 = h22f(hc.y), c2 = h22f(hc.z), c3 = h22f(hc.w);
            float4 o1, o2;
            o1.x = 0.25f * (a0.x + b0.x + c0.x + acc[0]);
            o1.y = 0.25f * (a0.y + b0.y + c0.y + acc[1]);
            o1.z = 0.25f * (a1.x + b1.x + c1.x + acc[2]);
            o1.w = 0.25f * (a1.y + b1.y + c1.y + acc[3]);
            o2.x = 0.25f * (a2.x + b2.x + c2.x + acc[4]);
            o2.y = 0.25f * (a2.y + b2.y + c2.y + acc[5]);
            o2.z = 0.25f * (a3.x + b3.x + c3.x + acc[6]);
            o2.w = 0.25f * (a3.y + b3.y + c3.y + acc[7]);
            __stcs(out + warp * 16 + 2 * l8,     o1);
            __stcs(out + warp * 16 + 2 * l8 + 1, o2);
        }
    }
}

extern "C" void kernel_launch(void* const* d_in, const int* in_sizes, int n_in,
                              void* d_out, int out_size) {
    // metadata order: user_emb, item_emb, adj_vals, adj_rows, adj_cols
    const float4* user = (const float4*)d_in[0];
    const float4* item = (const float4*)d_in[1];
    const float*  vals = (const float*)d_in[2];
    const int*    rows = (const int*)d_in[3];
    const int*    cols = (const int*)d_in[4];
    float4* out = (float4*)d_out;

    uint4 *bufA, *bufB, *bufC; int2* bkt;
    int *cnt, *offs, *cur, *bsum, *boff;
    cudaGetSymbolAddress((void**)&bufA, g_bufA);
    cudaGetSymbolAddress((void**)&bufB, g_bufB);
    cudaGetSymbolAddress((void**)&bufC, g_bufC);
    cudaGetSymbolAddress((void**)&bkt,  g_bkt);
    cudaGetSymbolAddress((void**)&cnt,  g_cnt);
    cudaGetSymbolAddress((void**)&offs, g_offs);
    cudaGetSymbolAddress((void**)&cur,  g_cur);
    cudaGetSymbolAddress((void**)&bsum, g_bsum);
    cudaGetSymbolAddress((void**)&boff, g_boff);

    const int TB = 256;
    const int initBlocks = (NH + TB - 1) / TB;
    const int e4Blocks   = (NNZ / 4 + TB - 1) / TB;
    const int rowBlocks  = (N_NODES + TB - 1) / TB;
    const int warpBlocks = (N_NODES * 32 + TB - 1) / TB;

    init_kernel<<<initBlocks, TB>>>(user, item, bufA, cnt);
    hist_kernel<<<e4Blocks, TB>>>((const int4*)rows, cnt);
    scan1_kernel<<<NB_SCAN, 1024>>>(cnt, bsum);
    scan2_kernel<<<1, 128>>>(bsum, boff, offs);
    scan3_kernel<<<NB_SCAN, 1024>>>(cnt, boff, offs, cur);
    pad_kernel<<<rowBlocks, TB>>>(bkt, cnt, offs);
    fill_kernel<<<e4Blocks, TB>>>((const int4*)rows, (const int4*)cols,
                                  (const float4*)vals, offs, bkt, cur);

    // layer 1: A -> B
    spmm_kernel<<<warpBlocks, TB>>>(bkt, offs, bufA, bufB, bufA, bufB, out, 0);
    // layer 2: B -> C
    spmm_kernel<<<warpBlocks, TB>>>(bkt, offs, bufB, bufC, bufA, bufB, out, 0);
    // layer 3: C -> out (fused: out = 0.25*(A + B + C + adj@C))
    spmm_kernel<<<warpBlocks, TB>>>(bkt, offs, bufC, bufC, bufA, bufB, out, 1);
}

// round 11
// speedup vs baseline: 1.0857x; 1.0857x over previous
#include <cuda_runtime.h>
#include <cuda_fp16.h>
#include <cstdint>

constexpr int USER_NUM = 200000;
constexpr int ITEM_NUM = 100000;
constexpr int N_NODES  = USER_NUM + ITEM_NUM;   // 300000
constexpr int NNZ      = 12800000;
constexpr int U4       = USER_NUM * 16;         // user float4 count
constexpr int H8       = 8;                     // uint4 (8 halves) per 64-wide fp16 row
constexpr int NH       = N_NODES * H8;          // 2.4M uint4 per fp16 buffer
constexpr int CAP      = 88;                    // bucket capacity (mean 42.7, max ~76)
constexpr int ROW_SPLIT = 150000;               // two-pass scatter window boundary

// Static device scratch
__device__ uint4 g_bufA[NH];                    // 38.4 MB fp16 (e0)
__device__ uint4 g_bufB[NH];                    // 38.4 MB fp16 (e1)
__device__ uint4 g_bufC[NH];                    // 38.4 MB fp16 (e2)
__device__ int2  g_bkt[(size_t)N_NODES * CAP];  // 211.2 MB (col, val_bits); halves ~105.6 MB
__device__ int   g_cnt[N_NODES];

__device__ __forceinline__ uint32_t f22h(float a, float b) {
    __half2 h = __floats2half2_rn(a, b);
    return reinterpret_cast<uint32_t&>(h);
}
__device__ __forceinline__ float2 h22f(uint32_t u) {
    __half2 h = reinterpret_cast<__half2&>(u);
    return __half22float2(h);
}

// ---------------------------------------------------------------------------
// init: bufA = fp16(concat(user, item)); cnt = 0.
// ---------------------------------------------------------------------------
__global__ void init_kernel(const float4* __restrict__ user,
                            const float4* __restrict__ item,
                            uint4* __restrict__ bufA,
                            int* __restrict__ cnt) {
    int i = blockIdx.x * blockDim.x + threadIdx.x;
    if (i < N_NODES) cnt[i] = 0;
    if (i >= NH) return;
    int f = i * 2;                              // float4 index (U4 is even)
    float4 x = (f < U4) ? __ldg(user + f)     : __ldg(item + f - U4);
    float4 y = (f < U4) ? __ldg(user + f + 1) : __ldg(item + f + 1 - U4);
    uint4 h;
    h.x = f22h(x.x, x.y);
    h.y = f22h(x.z, x.w);
    h.z = f22h(y.x, y.y);
    h.w = f22h(y.z, y.w);
    bufA[i] = h;
}

// ---------------------------------------------------------------------------
// bucket: scatter edges whose destination row is in [lo, hi) into their
// row's bucket. Called twice with disjoint row ranges so each pass's
// ~105 MB scatter window is L2-resident (write-allocated lines fill fully
// and write back once instead of thrashing partial lines to DRAM).
// Edge streams use .cs (evict-first); 4 edges per thread via 16B loads.
// ---------------------------------------------------------------------------
__global__ void bucket_kernel(const int4*   __restrict__ rows4,
                              const int4*   __restrict__ cols4,
                              const float4* __restrict__ vals4,
                              int2* __restrict__ bkt,
                              int*  __restrict__ cnt,
                              int lo, int hi) {
    int t = blockIdx.x * blockDim.x + threadIdx.x;
    if (t >= NNZ / 4) return;
    int4   r = __ldcs(rows4 + t);
    int4   c = __ldcs(cols4 + t);
    float4 v = __ldcs(vals4 + t);

    if (r.x >= lo && r.x < hi) {
        int p = atomicAdd(cnt + r.x, 1);
        if (p < CAP) bkt[(size_t)r.x * CAP + p] = make_int2(c.x, __float_as_int(v.x));
    }
    if (r.y >= lo && r.y < hi) {
        int p = atomicAdd(cnt + r.y, 1);
        if (p < CAP) bkt[(size_t)r.y * CAP + p] = make_int2(c.y, __float_as_int(v.y));
    }
    if (r.z >= lo && r.z < hi) {
        int p = atomicAdd(cnt + r.z, 1);
        if (p < CAP) bkt[(size_t)r.z * CAP + p] = make_int2(c.z, __float_as_int(v.z));
    }
    if (r.w >= lo && r.w < hi) {
        int p = atomicAdd(cnt + r.w, 1);
        if (p < CAP) bkt[(size_t)r.w * CAP + p] = make_int2(c.w, __float_as_int(v.w));
    }
}

// ---------------------------------------------------------------------------
// pad: zero-fill buckets up to the next multiple of 8 (col 0, val 0 -> +0).
// ---------------------------------------------------------------------------
__global__ void pad_kernel(int2* __restrict__ bkt, const int* __restrict__ cnt) {
    int r = blockIdx.x * blockDim.x + threadIdx.x;
    if (r >= N_NODES) return;
    int n  = min(__ldg(cnt + r), CAP);
    int n8 = min((n + 7) & ~7, CAP);
    int2* base = bkt + (size_t)r * CAP;
    for (int i = n; i < n8; ++i) base[i] = make_int2(0, 0);
}

// ---------------------------------------------------------------------------
// spmm: round-5 proven body (regs 32, occ ~84%). One warp per destination
// row; four 8-lane edge sub-streams; one LDG.128 warp-instruction gathers
// FOUR edges' 8-half slices; fp32 FFMA path; fused epilogue.
// final==0: dst[row] = fp16(acc).   final==1: out[row] = 0.25*(e0+e1+e2+acc).
// ---------------------------------------------------------------------------
__global__ void __launch_bounds__(256)
spmm_kernel(const int2* __restrict__ bkt,
            const int*  __restrict__ cnt,
            const uint4* __restrict__ src,
            uint4* __restrict__ dst,
            const uint4* __restrict__ eA,
            const uint4* __restrict__ eB,
            float4* __restrict__ out,
            int final_) {
    int warp = (blockIdx.x * blockDim.x + threadIdx.x) >> 5;
    int lane = threadIdx.x & 31;
    if (warp >= N_NODES) return;
    int sub = lane >> 3;       // edge sub-stream 0..3
    int l8  = lane & 7;        // uint4 slot within row

    int n  = min(__ldg(cnt + warp), CAP);
    int n8 = (n + 7) & ~7;
    const int2* base = bkt + (size_t)warp * CAP;

    float acc[8];
    #pragma unroll
    for (int k = 0; k < 8; ++k) acc[k] = 0.f;

    // software-pipelined edge metadata
    int2 p0 = make_int2(0, 0), p1 = make_int2(0, 0);
    if (n8 > 0) { p0 = __ldcs(base + sub); p1 = __ldcs(base + 4 + sub); }

    for (int c = 0; c < n8; c += 8) {
        int2 f0 = p0, f1 = p1;
        if (c + 8 < n8) {
            p0 = __ldcs(base + c + 8  + sub);
            p1 = __ldcs(base + c + 12 + sub);
        }
        {
            uint4 h = __ldg(src + f0.x * H8 + l8);
            float v = __int_as_float(f0.y);
            float2 a = h22f(h.x), b = h22f(h.y), cc = h22f(h.z), d = h22f(h.w);
            acc[0] += v * a.x; acc[1] += v * a.y;
            acc[2] += v * b.x; acc[3] += v * b.y;
            acc[4] += v * cc.x; acc[5] += v * cc.y;
            acc[6] += v * d.x; acc[7] += v * d.y;
        }
        {
            uint4 h = __ldg(src + f1.x * H8 + l8);
            float v = __int_as_float(f1.y);
            float2 a = h22f(h.x), b = h22f(h.y), cc = h22f(h.z), d = h22f(h.w);
            acc[0] += v * a.x; acc[1] += v * a.y;
            acc[2] += v * b.x; acc[3] += v * b.y;
            acc[4] += v * cc.x; acc[5] += v * cc.y;
            acc[6] += v * d.x; acc[7] += v * d.y;
        }
    }

    // combine the four sub-streams
    #pragma unroll
    for (int k = 0; k < 8; ++k) {
        acc[k] += __shfl_xor_sync(0xffffffffu, acc[k], 8);
        acc[k] += __shfl_xor_sync(0xffffffffu, acc[k], 16);
    }

    if (sub == 0) {
        int o = warp * H8 + l8;
        if (!final_) {
            uint4 h;
            h.x = f22h(acc[0], acc[1]);
            h.y = f22h(acc[2], acc[3]);
            h.z = f22h(acc[4], acc[5]);
            h.w = f22h(acc[6], acc[7]);
            dst[o] = h;
        } else {
            uint4 ha = __ldg(eA + o);
            uint4 hb = __ldg(eB + o);
            uint4 hc = __ldg(src + o);      // src == e2 buffer in final layer
            float2 a0 = h22f(ha.x), a1 = h22f(ha.y), a2 = h22f(ha.z), a3 = h22f(ha.w);
            float2 b0 = h22f(hb.x), b1 = h22f(hb.y), b2 = h22f(hb.z), b3 = h22f(hb.w);
            float2 c0 = h22f(hc.x), c1 = h22f(hc.y), c2 = h22f(hc.z), c3 = h22f(hc.w);
            float4 o1, o2;
            o1.x = 0.25f * (a0.x + b0.x + c0.x + acc[0]);
            o1.y = 0.25f * (a0.y + b0.y + c0.y + acc[1]);
            o1.z = 0.25f * (a1.x + b1.x + c1.x + acc[2]);
            o1.w = 0.25f * (a1.y + b1.y + c1.y + acc[3]);
            o2.x = 0.25f * (a2.x + b2.x + c2.x + acc[4]);
            o2.y = 0.25f * (a2.y + b2.y + c2.y + acc[5]);
            o2.z = 0.25f * (a3.x + b3.x + c3.x + acc[6]);
            o2.w = 0.25f * (a3.y + b3.y + c3.y + acc[7]);
            __stcs(out + warp * 16 + 2 * l8,     o1);
            __stcs(out + warp * 16 + 2 * l8 + 1, o2);
        }
    }
}

extern "C" void kernel_launch(void* const* d_in, const int* in_sizes, int n_in,
                              void* d_out, int out_size) {
    // metadata order: user_emb, item_emb, adj_vals, adj_rows, adj_cols
    const float4* user = (const float4*)d_in[0];
    const float4* item = (const float4*)d_in[1];
    const float*  vals = (const float*)d_in[2];
    const int*    rows = (const int*)d_in[3];
    const int*    cols = (const int*)d_in[4];
    float4* out = (float4*)d_out;

    uint4 *bufA, *bufB, *bufC; int2* bkt; int* cnt;
    cudaGetSymbolAddress((void**)&bufA, g_bufA);
    cudaGetSymbolAddress((void**)&bufB, g_bufB);
    cudaGetSymbolAddress((void**)&bufC, g_bufC);
    cudaGetSymbolAddress((void**)&bkt,  g_bkt);
    cudaGetSymbolAddress((void**)&cnt,  g_cnt);

    const int TB = 256;
    const int initBlocks = (NH + TB - 1) / TB;
    const int e4Blocks   = (NNZ / 4 + TB - 1) / TB;
    const int rowBlocks  = (N_NODES + TB - 1) / TB;
    const int warpBlocks = (N_NODES * 32 + TB - 1) / TB;

    init_kernel<<<initBlocks, TB>>>(user, item, bufA, cnt);
    // Two-pass scatter: each pass's bucket window (~105.6 MB) is L2-resident.
    bucket_kernel<<<e4Blocks, TB>>>((const int4*)rows, (const int4*)cols,
                                    (const float4*)vals, bkt, cnt, 0, ROW_SPLIT);
    bucket_kernel<<<e4Blocks, TB>>>((const int4*)rows, (const int4*)cols,
                                    (const float4*)vals, bkt, cnt, ROW_SPLIT, N_NODES);
    pad_kernel<<<rowBlocks, TB>>>(bkt, cnt);

    // layer 1: A -> B
    spmm_kernel<<<warpBlocks, TB>>>(bkt, cnt, bufA, bufB, bufA, bufB, out, 0);
    // layer 2: B -> C
    spmm_kernel<<<warpBlocks, TB>>>(bkt, cnt, bufB, bufC, bufA, bufB, out, 0);
    // layer 3: C -> out (fused: out = 0.25*(A + B + C + adj@C))
    spmm_kernel<<<warpBlocks, TB>>>(bkt, cnt, bufC, bufC, bufA, bufB, out, 1);
}

// round 12
// speedup vs baseline: 1.1168x; 1.0286x over previous
#include <cuda_runtime.h>
#include <cuda_fp16.h>
#include <cstdint>

constexpr int USER_NUM = 200000;
constexpr int ITEM_NUM = 100000;
constexpr int N_NODES  = USER_NUM + ITEM_NUM;   // 300000
constexpr int NNZ      = 12800000;
constexpr int U4       = USER_NUM * 16;         // user float4 count
constexpr int H8       = 8;                     // uint4 (8 halves) per 64-wide fp16 row
constexpr int NH       = N_NODES * H8;          // 2.4M uint4 per fp16 buffer
constexpr int CAP      = 96;                    // bucket capacity (mean 42.7, max ~76)

constexpr int TB          = 256;
constexpr int INIT_BLOCKS = (NH + TB - 1) / TB;        // 9375
constexpr int E4_BLOCKS   = (NNZ / 4 + TB - 1) / TB;   // 12500

// Static device scratch
__device__ uint4 g_bufA[NH];                    // 38.4 MB fp16 (e0)
__device__ uint4 g_bufB[NH];                    // 38.4 MB fp16 (e1)
__device__ uint4 g_bufC[NH];                    // 38.4 MB fp16 (e2)
__device__ int2  g_bkt[(size_t)N_NODES * CAP];  // 230.4 MB (col, val_bits)
__device__ int   g_cnt[N_NODES];

__device__ __forceinline__ uint32_t f22h(float a, float b) {
    __half2 h = __floats2half2_rn(a, b);
    return reinterpret_cast<uint32_t&>(h);
}
__device__ __forceinline__ float2 h22f(uint32_t u) {
    __half2 h = reinterpret_cast<__half2&>(u);
    return __half22float2(h);
}

// ---------------------------------------------------------------------------
// zero_cnt: cnt = 0 (must complete before any bucket block runs).
// ---------------------------------------------------------------------------
__global__ void zero_cnt_kernel(int* __restrict__ cnt) {
    int i = blockIdx.x * blockDim.x + threadIdx.x;
    if (i < N_NODES) cnt[i] = 0;
}

// ---------------------------------------------------------------------------
// fused init || bucket: blocks [0, INIT_BLOCKS) convert fp32 embeddings to
// the fp16 bufA; blocks [INIT_BLOCKS, ...) scatter edges into buckets.
// The two phases touch disjoint data, so the BW-bound init fills issue
// bubbles of the atomic-latency-bound bucket instead of serializing after it.
// ---------------------------------------------------------------------------
__global__ void init_bucket_kernel(const float4* __restrict__ user,
                                   const float4* __restrict__ item,
                                   uint4* __restrict__ bufA,
                                   const int4*   __restrict__ rows4,
                                   const int4*   __restrict__ cols4,
                                   const float4* __restrict__ vals4,
                                   int2* __restrict__ bkt,
                                   int*  __restrict__ cnt) {
    if (blockIdx.x < INIT_BLOCKS) {
        int i = blockIdx.x * blockDim.x + threadIdx.x;
        if (i >= NH) return;
        int f = i * 2;                          // float4 index (U4 is even)
        float4 x = (f < U4) ? __ldg(user + f)     : __ldg(item + f - U4);
        float4 y = (f < U4) ? __ldg(user + f + 1) : __ldg(item + f + 1 - U4);
        uint4 h;
        h.x = f22h(x.x, x.y);
        h.y = f22h(x.z, x.w);
        h.z = f22h(y.x, y.y);
        h.w = f22h(y.z, y.w);
        bufA[i] = h;
    } else {
        int t = (blockIdx.x - INIT_BLOCKS) * blockDim.x + threadIdx.x;
        if (t >= NNZ / 4) return;
        int4   r = __ldcs(rows4 + t);
        int4   c = __ldcs(cols4 + t);
        float4 v = __ldcs(vals4 + t);

        int p0 = atomicAdd(cnt + r.x, 1);
        if (p0 < CAP) bkt[(size_t)r.x * CAP + p0] = make_int2(c.x, __float_as_int(v.x));
        int p1 = atomicAdd(cnt + r.y, 1);
        if (p1 < CAP) bkt[(size_t)r.y * CAP + p1] = make_int2(c.y, __float_as_int(v.y));
        int p2 = atomicAdd(cnt + r.z, 1);
        if (p2 < CAP) bkt[(size_t)r.z * CAP + p2] = make_int2(c.z, __float_as_int(v.z));
        int p3 = atomicAdd(cnt + r.w, 1);
        if (p3 < CAP) bkt[(size_t)r.w * CAP + p3] = make_int2(c.w, __float_as_int(v.w));
    }
}

// ---------------------------------------------------------------------------
// pad8: 8 threads per row; each writes at most ONE zero slot in [n, n8).
// (Slot i = (n & ~7) + s for s in 0..7, kept iff n <= i < n8.)
// ---------------------------------------------------------------------------
__global__ void pad8_kernel(int2* __restrict__ bkt, const int* __restrict__ cnt) {
    int t = blockIdx.x * blockDim.x + threadIdx.x;
    int r = t >> 3;
    int s = t & 7;
    if (r >= N_NODES) return;
    int n  = min(__ldg(cnt + r), CAP);
    int n8 = min((n + 7) & ~7, CAP);
    int i  = (n & ~7) + s;
    if (i >= n && i < n8) bkt[(size_t)r * CAP + i] = make_int2(0, 0);
}

// ---------------------------------------------------------------------------
// spmm: round-5 proven body (regs 32, occ ~84%). One warp per destination
// row; four 8-lane edge sub-streams; one LDG.128 warp-instruction gathers
// FOUR edges' 8-half slices; fp32 FFMA path; fused epilogue.
// final==0: dst[row] = fp16(acc).   final==1: out[row] = 0.25*(e0+e1+e2+acc).
// ---------------------------------------------------------------------------
__global__ void __launch_bounds__(256)
spmm_kernel(const int2* __restrict__ bkt,
            const int*  __restrict__ cnt,
            const uint4* __restrict__ src,
            uint4* __restrict__ dst,
            const uint4* __restrict__ eA,
            const uint4* __restrict__ eB,
            float4* __restrict__ out,
            int final_) {
    int warp = (blockIdx.x * blockDim.x + threadIdx.x) >> 5;
    int lane = threadIdx.x & 31;
    if (warp >= N_NODES) return;
    int sub = lane >> 3;       // edge sub-stream 0..3
    int l8  = lane & 7;        // uint4 slot within row

    int n  = min(__ldg(cnt + warp), CAP);
    int n8 = (n + 7) & ~7;
    const int2* base = bkt + (size_t)warp * CAP;

    float acc[8];
    #pragma unroll
    for (int k = 0; k < 8; ++k) acc[k] = 0.f;

    // software-pipelined edge metadata
    int2 p0 = make_int2(0, 0), p1 = make_int2(0, 0);
    if (n8 > 0) { p0 = __ldcs(base + sub); p1 = __ldcs(base + 4 + sub); }

    for (int c = 0; c < n8; c += 8) {
        int2 f0 = p0, f1 = p1;
        if (c + 8 < n8) {
            p0 = __ldcs(base + c + 8  + sub);
            p1 = __ldcs(base + c + 12 + sub);
        }
        {
            uint4 h = __ldg(src + f0.x * H8 + l8);
            float v = __int_as_float(f0.y);
            float2 a = h22f(h.x), b = h22f(h.y), cc = h22f(h.z), d = h22f(h.w);
            acc[0] += v * a.x; acc[1] += v * a.y;
            acc[2] += v * b.x; acc[3] += v * b.y;
            acc[4] += v * cc.x; acc[5] += v * cc.y;
            acc[6] += v * d.x; acc[7] += v * d.y;
        }
        {
            uint4 h = __ldg(src + f1.x * H8 + l8);
            float v = __int_as_float(f1.y);
            float2 a = h22f(h.x), b = h22f(h.y), cc = h22f(h.z), d = h22f(h.w);
            acc[0] += v * a.x; acc[1] += v * a.y;
            acc[2] += v * b.x; acc[3] += v * b.y;
            acc[4] += v * cc.x; acc[5] += v * cc.y;
            acc[6] += v * d.x; acc[7] += v * d.y;
        }
    }

    // combine the four sub-streams
    #pragma unroll
    for (int k = 0; k < 8; ++k) {
        acc[k] += __shfl_xor_sync(0xffffffffu, acc[k], 8);
        acc[k] += __shfl_xor_sync(0xffffffffu, acc[k], 16);
    }

    if (sub == 0) {
        int o = warp * H8 + l8;
        if (!final_) {
            uint4 h;
            h.x = f22h(acc[0], acc[1]);
            h.y = f22h(acc[2], acc[3]);
            h.z = f22h(acc[4], acc[5]);
            h.w = f22h(acc[6], acc[7]);
            dst[o] = h;
        } else {
            uint4 ha = __ldg(eA + o);
            uint4 hb = __ldg(eB + o);
            uint4 hc = __ldg(src + o);      // src == e2 buffer in final layer
            float2 a0 = h22f(ha.x), a1 = h22f(ha.y), a2 = h22f(ha.z), a3 = h22f(ha.w);
            float2 b0 = h22f(hb.x), b1 = h22f(hb.y), b2 = h22f(hb.z), b3 = h22f(hb.w);
            float2 c0 = h22f(hc.x), c1 = h22f(hc.y), c2 = h22f(hc.z), c3 = h22f(hc.w);
            float4 o1, o2;
            o1.x = 0.25f * (a0.x + b0.x + c0.x + acc[0]);
            o1.y = 0.25f * (a0.y + b0.y + c0.y + acc[1]);
            o1.z = 0.25f * (a1.x + b1.x + c1.x + acc[2]);
            o1.w = 0.25f * (a1.y + b1.y + c1.y + acc[3]);
            o2.x = 0.25f * (a2.x + b2.x + c2.x + acc[4]);
            o2.y = 0.25f * (a2.y + b2.y + c2.y + acc[5]);
            o2.z = 0.25f * (a3.x + b3.x + c3.x + acc[6]);
            o2.w = 0.25f * (a3.y + b3.y + c3.y + acc[7]);
            __stcs(out + warp * 16 + 2 * l8,     o1);
            __stcs(out + warp * 16 + 2 * l8 + 1, o2);
        }
    }
}

extern "C" void kernel_launch(void* const* d_in, const int* in_sizes, int n_in,
                              void* d_out, int out_size) {
    // metadata order: user_emb, item_emb, adj_vals, adj_rows, adj_cols
    const float4* user = (const float4*)d_in[0];
    const float4* item = (const float4*)d_in[1];
    const float*  vals = (const float*)d_in[2];
    const int*    rows = (const int*)d_in[3];
    const int*    cols = (const int*)d_in[4];
    float4* out = (float4*)d_out;

    uint4 *bufA, *bufB, *bufC; int2* bkt; int* cnt;
    cudaGetSymbolAddress((void**)&bufA, g_bufA);
    cudaGetSymbolAddress((void**)&bufB, g_bufB);
    cudaGetSymbolAddress((void**)&bufC, g_bufC);
    cudaGetSymbolAddress((void**)&bkt,  g_bkt);
    cudaGetSymbolAddress((void**)&cnt,  g_cnt);

    const int cntBlocks  = (N_NODES + TB - 1) / TB;
    const int padBlocks  = (N_NODES * 8 + TB - 1) / TB;
    const int warpBlocks = (N_NODES * 32 + TB - 1) / TB;

    zero_cnt_kernel<<<cntBlocks, TB>>>(cnt);
    init_bucket_kernel<<<INIT_BLOCKS + E4_BLOCKS, TB>>>(
        user, item, bufA,
        (const int4*)rows, (const int4*)cols, (const float4*)vals, bkt, cnt);
    pad8_kernel<<<padBlocks, TB>>>(bkt, cnt);

    // layer 1: A -> B
    spmm_kernel<<<warpBlocks, TB>>>(bkt, cnt, bufA, bufB, bufA, bufB, out, 0);
    // layer 2: B -> C
    spmm_kernel<<<warpBlocks, TB>>>(bkt, cnt, bufB, bufC, bufA, bufB, out, 0);
    // layer 3: C -> out (fused: out = 0.25*(A + B + C + adj@C))
    spmm_kernel<<<warpBlocks, TB>>>(bkt, cnt, bufC, bufC, bufA, bufB, out, 1);
}